// round 12
// baseline (speedup 1.0000x reference)
#include <cuda_runtime.h>
#include <math.h>

constexpr int NB  = 2;
constexpr int IC  = 64;
constexpr int IH  = 80;
constexpr int IW  = 80;
constexpr int IHW = IH * IW;   // 6400
constexpr int NSPLIT  = 4;
constexpr int CICHUNK = IC / NSPLIT;   // 16

// Concatenated offset/mask layouts (branch bases)
constexpr int OFF_B3 = 0;
constexpr int OFF_B5 = NB * 18 * IHW;
constexpr int OFF_B7 = OFF_B5 + NB * 50 * IHW;
constexpr int OFF_TOT = OFF_B7 + NB * 98 * IHW;
constexpr int MSK_B3 = 0;
constexpr int MSK_B5 = NB * 9 * IHW;
constexpr int MSK_B7 = MSK_B5 + NB * 25 * IHW;
constexpr int MSK_TOT = MSK_B7 + NB * 49 * IHW;
constexpr int WT_B3 = 0;
constexpr int WT_B5 = 9 * 4096;
constexpr int WT_B7 = (9 + 25) * 4096;
constexpr int PCH   = NB * 64 * IHW;

// conv-weight (offset+mask, transposed) bases: [ci][grp][tap][16co]
constexpr int CW_B3 = 0;
constexpr int CW_L3 = 64 * 2 * 9 * 16;
constexpr int CW_B5 = CW_B3 + CW_L3;
constexpr int CW_L5 = 64 * 5 * 25 * 16;
constexpr int CW_B7 = CW_B5 + CW_L5;
constexpr int CW_L7 = 64 * 10 * 49 * 16;
constexpr int CW_TOT = CW_B7 + CW_L7;
constexpr int WT_TOT = (9 + 25 + 49) * 4096;

__device__ float g_offP[NSPLIT * OFF_TOT];
__device__ float g_mskP[NSPLIT * MSK_TOT];
__device__ float g_offF[OFF_TOT];
__device__ float g_mskF[MSK_TOT];
__device__ float g_wt[WT_TOT];        // dcn weights, c-major: [kk][c*64 + o]
__device__ float g_cw[CW_TOT];        // conv weights transposed
__device__ float g_outP5[2 * PCH];
__device__ float g_outP7[4 * PCH];
__device__ __align__(16) float g_xT[NB * IHW * IC];  // NHWC copy of x for sampler

// ---- f32x2 packed helpers (sm_103a) ----
using u64 = unsigned long long;
__device__ __forceinline__ u64 pack2(float a, float b) {
    u64 r; asm("mov.b64 %0, {%1, %2};" : "=l"(r) : "f"(a), "f"(b)); return r;
}
__device__ __forceinline__ void ffma2(u64& d, u64 a, u64 b) {
    asm("fma.rn.f32x2 %0, %1, %2, %3;" : "=l"(d) : "l"(a), "l"(b), "l"(d));
}
__device__ __forceinline__ float2 unpack2(u64 v) {
    float x, y; asm("mov.b64 {%0, %1}, %2;" : "=f"(x), "=f"(y) : "l"(v));
    return make_float2(x, y);
}

// ---------------------------------------------------------------------------
// NHWC transpose: xT[((b*IHW)+pix)*64 + c] = x[(b*64+c)*IHW + pix]
// 400 blocks x 256 threads, 32 pixels x 64 channels per block, smem-tiled.
// ---------------------------------------------------------------------------
__global__ void transpose_x(const float* __restrict__ x)
{
    __shared__ float s[64 * 33];
    const int tid  = threadIdx.x;
    const int pix0 = blockIdx.x * 32;
    const int b    = pix0 / IHW;
    const int rem0 = pix0 - b * IHW;

    for (int i = tid; i < 2048; i += 256) {
        const int c = i >> 5, p = i & 31;
        s[c * 33 + p] = x[(b * IC + c) * IHW + rem0 + p];
    }
    __syncthreads();
    for (int i = tid; i < 2048; i += 256) {
        const int p = i >> 6, c = i & 63;
        g_xT[((size_t)b * IHW + rem0 + p) * IC + c] = s[c * 33 + p];
    }
}

// ---------------------------------------------------------------------------
// Prep: transpose conv weights + dcn weights
// ---------------------------------------------------------------------------
template<int K, int NG>
__device__ __forceinline__ void cw_fill(
    int j, int base, const float* __restrict__ wo, const float* __restrict__ wm)
{
    constexpr int KK = K * K;
    const int lc  = j & 15;
    const int tap = (j >> 4) % KK;
    const int t   = (j >> 4) / KK;
    const int grp = t % NG;
    const int ci  = t / NG;
    const int co  = grp * 16 + lc;
    float v = 0.f;
    if (co < 2 * KK)        v = wo[(co * IC + ci) * KK + tap];
    else if (co < 3 * KK)   v = wm[((co - 2 * KK) * IC + ci) * KK + tap];
    g_cw[base + j] = v;
}

__global__ void prep_weights(
    const float* __restrict__ w3o, const float* __restrict__ w3m,
    const float* __restrict__ w5o, const float* __restrict__ w5m,
    const float* __restrict__ w7o, const float* __restrict__ w7m,
    const float* __restrict__ d3,  const float* __restrict__ d5,
    const float* __restrict__ d7)
{
    int i = blockIdx.x * 256 + threadIdx.x;
    if (i < CW_TOT) {
        if (i < CW_B5)       cw_fill<3, 2>(i,          CW_B3, w3o, w3m);
        else if (i < CW_B7)  cw_fill<5, 5>(i - CW_B5,  CW_B5, w5o, w5m);
        else                 cw_fill<7,10>(i - CW_B7,  CW_B7, w7o, w7m);
    } else {
        int i2 = i - CW_TOT;
        if (i2 < WT_TOT) {
            if (i2 < WT_B5) {
                int kk = i2 >> 12, r = i2 & 4095, c = r >> 6, o = r & 63;
                g_wt[i2] = d3[(o * 64 + c) * 9 + kk];
            } else if (i2 < WT_B7) {
                int j = i2 - WT_B5;
                int kk = j >> 12, r = j & 4095, c = r >> 6, o = r & 63;
                g_wt[i2] = d5[(o * 64 + c) * 25 + kk];
            } else {
                int j = i2 - WT_B7;
                int kk = j >> 12, r = j & 4095, c = r >> 6, o = r & 63;
                g_wt[i2] = d7[(o * 64 + c) * 49 + kk];
            }
        }
    }
}

// ---------------------------------------------------------------------------
// Conv body: 16x16 spatial tile, 128 threads, 2 px x 16 co, split-K over ci.
// Double-buffered smem, register prefetch, 1 sync per ci.
// ---------------------------------------------------------------------------
template<int K, int NG>
__device__ __forceinline__ void conv_body(
    int lb, const float* __restrict__ x, int cwbase,
    int offbase, int mskbase, float* sx2, float* sw2)
{
    constexpr int KK  = K * K;
    constexpr int PAD = K / 2;
    constexpr int TS  = 16 + K - 1;
    constexpr int P   = TS | 1;
    constexpr int WN  = KK * 16;
    constexpr int WLOAD = (WN + 127) / 128;
    constexpr int TN  = TS * TS;
    constexpr int TLOAD = (TN + 127) / 128;
    constexpr int SXSZ = TS * P;

    const int s    = lb & 3;
    int r          = lb >> 2;
    const int tile = r % 25;  r /= 25;
    const int grp  = r % NG;
    const int b    = r / NG;

    const int tid = threadIdx.x;
    const int tx  = tid & 15;
    const int ty  = tid >> 4;
    const int bx0 = (tile % 5) * 16;
    const int by0 = (tile / 5) * 16;
    const int co0 = grp * 16;
    const int ci0 = s * CICHUNK;

    u64 acc0[8], acc1[8];
    #pragma unroll
    for (int i = 0; i < 8; i++) { acc0[i] = 0ull; acc1[i] = 0ull; }

    float treg[TLOAD];
    float wreg[WLOAD];

    auto fetch = [&](int ci) {
        const float* xp = x + (b * IC + ci) * IHW;
        #pragma unroll
        for (int j = 0; j < TLOAD; j++) {
            const int idx = tid + j * 128;
            float v = 0.f;
            if (idx < TN) {
                const int ry = idx / TS, rx = idx - ry * TS;
                const int gy = by0 - PAD + ry, gx = bx0 - PAD + rx;
                if (gy >= 0 && gy < IH && gx >= 0 && gx < IW) v = xp[gy * IW + gx];
            }
            treg[j] = v;
        }
        const float* wp = g_cw + cwbase + (size_t)(ci * NG + grp) * WN;
        #pragma unroll
        for (int j = 0; j < WLOAD; j++) {
            const int idx = tid + j * 128;
            wreg[j] = (idx < WN) ? wp[idx] : 0.f;
        }
    };
    auto stage = [&](int buf) {
        float* sx = sx2 + buf * SXSZ;
        #pragma unroll
        for (int j = 0; j < TLOAD; j++) {
            const int idx = tid + j * 128;
            if (idx < TN) {
                const int ry = idx / TS, rx = idx - ry * TS;
                sx[ry * P + rx] = treg[j];
            }
        }
        float* sw = sw2 + buf * WN;
        #pragma unroll
        for (int j = 0; j < WLOAD; j++) {
            const int idx = tid + j * 128;
            if (idx < WN) sw[idx] = wreg[j];
        }
    };

    fetch(ci0);
    stage(0);
    __syncthreads();

    for (int ss = 0; ss < CICHUNK; ss++) {
        if (ss + 1 < CICHUNK) fetch(ci0 + ss + 1);

        const float* sx = sx2 + (ss & 1) * SXSZ;
        const float* sw = sw2 + (ss & 1) * WN;
        #pragma unroll
        for (int tap = 0; tap < KK; tap++) {
            const int dy = tap / K, dx = tap - dy * K;
            const float xv0 = sx[(ty + dy) * P + tx + dx];
            const float xv1 = sx[(ty + 8 + dy) * P + tx + dx];
            const u64 xp0 = pack2(xv0, xv0);
            const u64 xp1 = pack2(xv1, xv1);
            const u64* w2 = reinterpret_cast<const u64*>(&sw[tap * 16]);
            #pragma unroll
            for (int i = 0; i < 8; i++) {
                u64 w = w2[i];
                ffma2(acc0[i], xp0, w);
                ffma2(acc1[i], xp1, w);
            }
        }

        if (ss + 1 < CICHUNK) stage((ss + 1) & 1);
        __syncthreads();
    }

    float* op = g_offP + (size_t)s * OFF_TOT + offbase;
    float* mp = g_mskP + (size_t)s * MSK_TOT + mskbase;
    const int oy = by0 + ty, ox = bx0 + tx;
    const int idx0 = oy * IW + ox;
    const int idx1 = (oy + 8) * IW + ox;
    #pragma unroll
    for (int i = 0; i < 8; i++) {
        float2 v0 = unpack2(acc0[i]);
        float2 v1 = unpack2(acc1[i]);
        #pragma unroll
        for (int h = 0; h < 2; h++) {
            const int co = co0 + 2 * i + h;
            const float a0 = h ? v0.y : v0.x;
            const float a1 = h ? v1.y : v1.x;
            if (co < 2 * KK) {
                op[(b * 2 * KK + co) * IHW + idx0] = a0;
                op[(b * 2 * KK + co) * IHW + idx1] = a1;
            } else if (co < 3 * KK) {
                const int cm = co - 2 * KK;
                mp[(b * KK + cm) * IHW + idx0] = a0;
                mp[(b * KK + cm) * IHW + idx1] = a1;
            }
        }
    }
}

// Merged conv, branch-interleaved: groups of 17 blocks = 2 k3 + 5 k5 + 10 k7.
__global__ void __launch_bounds__(128) conv_all(const float* __restrict__ x)
{
    __shared__ __align__(16) float sx2[2 * 22 * 23];
    __shared__ __align__(16) float sw2[2 * 49 * 16];

    const int g = blockIdx.x / 17;
    const int u = blockIdx.x % 17;

    if (u < 2)
        conv_body<3, 2>(g * 2 + u,        x, CW_B3, OFF_B3, MSK_B3, sx2, sw2);
    else if (u < 7)
        conv_body<5, 5>(g * 5 + (u - 2),  x, CW_B5, OFF_B5, MSK_B5, sx2, sw2);
    else
        conv_body<7,10>(g * 10 + (u - 7), x, CW_B7, OFF_B7, MSK_B7, sx2, sw2);
}

// ---------------------------------------------------------------------------
// Reduce conv partials: offsets += bias; masks = sigmoid(sum + bias)
// ---------------------------------------------------------------------------
__global__ void reduce_offmask(
    const float* __restrict__ b3o, const float* __restrict__ b3m,
    const float* __restrict__ b5o, const float* __restrict__ b5m,
    const float* __restrict__ b7o, const float* __restrict__ b7m)
{
    int i = blockIdx.x * 256 + threadIdx.x;
    if (i < OFF_TOT) {
        float v = g_offP[i] + g_offP[OFF_TOT + i]
                + g_offP[2 * OFF_TOT + i] + g_offP[3 * (size_t)OFF_TOT + i];
        const float* bp; int local, kk2;
        if (i < OFF_B5)      { bp = b3o; local = i;          kk2 = 18; }
        else if (i < OFF_B7) { bp = b5o; local = i - OFF_B5; kk2 = 50; }
        else                 { bp = b7o; local = i - OFF_B7; kk2 = 98; }
        int co = (local / IHW) % kk2;
        g_offF[i] = v + bp[co];
    } else {
        int j = i - OFF_TOT;
        if (j < MSK_TOT) {
            float v = g_mskP[j] + g_mskP[MSK_TOT + j]
                    + g_mskP[2 * MSK_TOT + j] + g_mskP[3 * (size_t)MSK_TOT + j];
            const float* bp; int local, kk;
            if (j < MSK_B5)      { bp = b3m; local = j;          kk = 9;  }
            else if (j < MSK_B7) { bp = b5m; local = j - MSK_B5; kk = 25; }
            else                 { bp = b7m; local = j - MSK_B7; kk = 49; }
            int cm = (local / IHW) % kk;
            g_mskF[j] = 1.f / (1.f + expf(-(v + bp[cm])));
        }
    }
}

// ---------------------------------------------------------------------------
// Sample body: 128 pixels/block, 256 threads, taps [kk0,kk1).
// Gather: thread = 1 pixel x 32 channels via NHWC float4 loads (4 corners).
// Matvec: thread = 4 o x 8 px, f32x2 over pixel pairs.
// ---------------------------------------------------------------------------
template<int K>
__device__ __forceinline__ void sample_body(
    int tile, float* __restrict__ outp,
    int CS, int kk0, int kk1,
    int offbase, int mskbase, int wtbase,
    float* s_w, float* s_samp)
{
    constexpr int KK  = K * K;
    constexpr int PAD = K / 2;
    constexpr int SP  = 128;

    const float* offp = g_offF + offbase;
    const float* mskp = g_mskF + mskbase;
    const float* wtp  = g_wt  + wtbase;

    const int tid  = threadIdx.x;
    const int pix0 = tile * 128;
    const int b    = pix0 / IHW;
    const int rem0 = pix0 - b * IHW;

    const int o0 = tid & 15;
    const int pb = (tid >> 4) * 8;
    const int sp = tid & 127;
    const int sc = tid >> 7;

    const int rem = rem0 + sp;
    const int ph  = rem / IW;
    const int pw  = rem - ph * IW;

    u64 acc[4][4];
    #pragma unroll
    for (int q = 0; q < 4; q++)
        #pragma unroll
        for (int j = 0; j < 4; j++) acc[q][j] = 0ull;

    for (int kk = kk0; kk < kk1; kk++) {
        float4 wr[4];
        const float4* wsrc = reinterpret_cast<const float4*>(wtp + kk * 4096);
        #pragma unroll
        for (int j = 0; j < 4; j++) wr[j] = wsrc[tid + 256 * j];

        {
            const float oy = offp[(b * 2 * KK + 2 * kk    ) * IHW + rem];
            const float ox = offp[(b * 2 * KK + 2 * kk + 1) * IHW + rem];
            const float m  = mskp[(b * KK + kk) * IHW + rem];
            const float py = (float)(ph - PAD + kk / K) + oy;
            const float px = (float)(pw - PAD + kk % K) + ox;
            const float y0f = floorf(py), x0f = floorf(px);
            const int   y0  = (int)y0f,   x0  = (int)x0f;
            const float wy1 = py - y0f, wx1 = px - x0f;
            const float wy0 = 1.f - wy1, wx0 = 1.f - wx1;
            const bool vy0 = (y0 >= 0) && (y0 < IH);
            const bool vy1 = (y0 + 1 >= 0) && (y0 + 1 < IH);
            const bool vx0 = (x0 >= 0) && (x0 < IW);
            const bool vx1 = (x0 + 1 >= 0) && (x0 + 1 < IW);
            const int y0c = min(max(y0, 0), IH - 1);
            const int y1c = min(max(y0 + 1, 0), IH - 1);
            const int x0c = min(max(x0, 0), IW - 1);
            const int x1c = min(max(x0 + 1, 0), IW - 1);
            const float w00 = wy0 * wx0 * ((vy0 && vx0) ? 1.f : 0.f) * m;
            const float w01 = wy0 * wx1 * ((vy0 && vx1) ? 1.f : 0.f) * m;
            const float w10 = wy1 * wx0 * ((vy1 && vx0) ? 1.f : 0.f) * m;
            const float w11 = wy1 * wx1 * ((vy1 && vx1) ? 1.f : 0.f) * m;
            // NHWC corner base pointers (channel group sc*32, float4 over c)
            const float* bx = g_xT + ((size_t)b * IHW) * IC + sc * 32;
            const float* p00 = bx + (size_t)(y0c * IW + x0c) * IC;
            const float* p01 = bx + (size_t)(y0c * IW + x1c) * IC;
            const float* p10 = bx + (size_t)(y1c * IW + x0c) * IC;
            const float* p11 = bx + (size_t)(y1c * IW + x1c) * IC;
            float* sout = s_samp + (sc * 32) * SP + sp;
            #pragma unroll
            for (int j = 0; j < 8; j++) {
                const float4 a = *(const float4*)(p00 + 4 * j);
                const float4 bq = *(const float4*)(p01 + 4 * j);
                const float4 cq = *(const float4*)(p10 + 4 * j);
                const float4 dq = *(const float4*)(p11 + 4 * j);
                sout[(4 * j + 0) * SP] = w00 * a.x + w01 * bq.x + w10 * cq.x + w11 * dq.x;
                sout[(4 * j + 1) * SP] = w00 * a.y + w01 * bq.y + w10 * cq.y + w11 * dq.y;
                sout[(4 * j + 2) * SP] = w00 * a.z + w01 * bq.z + w10 * cq.z + w11 * dq.z;
                sout[(4 * j + 3) * SP] = w00 * a.w + w01 * bq.w + w10 * cq.w + w11 * dq.w;
            }
        }

        {
            float4* wdst = reinterpret_cast<float4*>(s_w);
            #pragma unroll
            for (int j = 0; j < 4; j++) wdst[tid + 256 * j] = wr[j];
        }
        __syncthreads();

        #pragma unroll 8
        for (int c = 0; c < 64; c++) {
            const float* wrow = &s_w[c * 64];
            const float4 sA = *(const float4*)&s_samp[c * SP + pb];
            const float4 sB = *(const float4*)&s_samp[c * SP + pb + 4];
            const u64 s0 = pack2(sA.x, sA.y);
            const u64 s1 = pack2(sA.z, sA.w);
            const u64 s2 = pack2(sB.x, sB.y);
            const u64 s3 = pack2(sB.z, sB.w);
            #pragma unroll
            for (int q = 0; q < 4; q++) {
                const float wv = wrow[o0 + 16 * q];
                const u64 wp = pack2(wv, wv);
                ffma2(acc[q][0], wp, s0);
                ffma2(acc[q][1], wp, s1);
                ffma2(acc[q][2], wp, s2);
                ffma2(acc[q][3], wp, s3);
            }
        }
        __syncthreads();
    }

    #pragma unroll
    for (int q = 0; q < 4; q++) {
        const int oo = o0 + q * 16;
        #pragma unroll
        for (int j = 0; j < 4; j++) {
            float2 v = unpack2(acc[q][j]);
            s_samp[oo * SP + pb + 2 * j]     = v.x;
            s_samp[oo * SP + pb + 2 * j + 1] = v.y;
        }
    }
    __syncthreads();
    for (int i = tid; i < 8192; i += 256) {
        const int oo = i >> 7, p = i & 127;
        outp[(b * CS + oo) * IHW + rem0 + p] = s_samp[oo * SP + p];
    }
}

// Balanced sampler: 700 blocks = 100 tiles x 7 tap-chunk units, interleaved.
extern __shared__ float smem_dyn[];
__global__ void __launch_bounds__(256, 2) sample_all(float* __restrict__ out)
{
    float* s_w    = smem_dyn;
    float* s_samp = smem_dyn + 4096;

    const int unit = blockIdx.x % 7;
    const int tile = blockIdx.x / 7;

    if (unit == 0) {
        sample_body<3>(tile, out, 192, 0, 9,
                       OFF_B3, MSK_B3, WT_B3, s_w, s_samp);
    } else if (unit <= 2) {
        const int c = unit - 1;
        const int k0 = c * 13, k1 = (c == 1) ? 25 : 13;
        sample_body<5>(tile, g_outP5 + (size_t)c * PCH, 64, k0, k1,
                       OFF_B5, MSK_B5, WT_B5, s_w, s_samp);
    } else {
        const int c = unit - 3;
        const int k0 = c * 13, k1 = (c == 3) ? 49 : (c + 1) * 13;
        sample_body<7>(tile, g_outP7 + (size_t)c * PCH, 64, k0, k1,
                       OFF_B7, MSK_B7, WT_B7, s_w, s_samp);
    }
}

// Fold k5/k7 partials into out channels [64,192)
__global__ void reduce_out(float* __restrict__ out)
{
    int i = blockIdx.x * 256 + threadIdx.x;
    if (i < PCH) {
        const int b     = i / (64 * IHW);
        const int local = i - b * 64 * IHW;
        out[(b * 192 + 64) * IHW + local]  = g_outP5[i] + g_outP5[PCH + i];
        out[(b * 192 + 128) * IHW + local] = g_outP7[i] + g_outP7[PCH + i]
                                           + g_outP7[2 * (size_t)PCH + i]
                                           + g_outP7[3 * (size_t)PCH + i];
    }
}

// ---------------------------------------------------------------------------
extern "C" void kernel_launch(void* const* d_in, const int* in_sizes, int n_in,
                              void* d_out, int out_size)
{
    const float* x = (const float*)d_in[0];
    float* out = (float*)d_out;

    transpose_x<<<NB * IHW / 32, 256>>>(x);

    prep_weights<<<(CW_TOT + WT_TOT + 255) / 256, 256>>>(
        (const float*)d_in[1],  (const float*)d_in[3],
        (const float*)d_in[6],  (const float*)d_in[8],
        (const float*)d_in[11], (const float*)d_in[13],
        (const float*)d_in[5],  (const float*)d_in[10], (const float*)d_in[15]);

    conv_all<<<3400, 128>>>(x);

    reduce_offmask<<<(OFF_TOT + MSK_TOT + 255) / 256, 256>>>(
        (const float*)d_in[2],  (const float*)d_in[4],
        (const float*)d_in[7],  (const float*)d_in[9],
        (const float*)d_in[12], (const float*)d_in[14]);

    sample_all<<<700, 256, 48 * 1024>>>(out);

    reduce_out<<<(PCH + 255) / 256, 256>>>(out);
}

// round 14
// speedup vs baseline: 1.1336x; 1.1336x over previous
#include <cuda_runtime.h>
#include <math.h>

constexpr int NB  = 2;
constexpr int IC  = 64;
constexpr int IH  = 80;
constexpr int IW  = 80;
constexpr int IHW = IH * IW;   // 6400
constexpr int NSPLIT  = 4;
constexpr int CICHUNK = IC / NSPLIT;   // 16

// Concatenated offset/mask layouts (branch bases)
constexpr int OFF_B3 = 0;
constexpr int OFF_B5 = NB * 18 * IHW;
constexpr int OFF_B7 = OFF_B5 + NB * 50 * IHW;
constexpr int OFF_TOT = OFF_B7 + NB * 98 * IHW;
constexpr int MSK_B3 = 0;
constexpr int MSK_B5 = NB * 9 * IHW;
constexpr int MSK_B7 = MSK_B5 + NB * 25 * IHW;
constexpr int MSK_TOT = MSK_B7 + NB * 49 * IHW;
constexpr int WT_B3 = 0;
constexpr int WT_B5 = 9 * 4096;
constexpr int WT_B7 = (9 + 25) * 4096;
constexpr int PCH   = NB * 64 * IHW;

// conv-weight (offset+mask, transposed) bases: [ci][grp][tap][16co]
constexpr int CW_B3 = 0;
constexpr int CW_L3 = 64 * 2 * 9 * 16;
constexpr int CW_B5 = CW_B3 + CW_L3;
constexpr int CW_L5 = 64 * 5 * 25 * 16;
constexpr int CW_B7 = CW_B5 + CW_L5;
constexpr int CW_L7 = 64 * 10 * 49 * 16;
constexpr int CW_TOT = CW_B7 + CW_L7;
constexpr int WT_TOT = (9 + 25 + 49) * 4096;

__device__ float g_offP[NSPLIT * OFF_TOT];   // split-K conv partials (offsets)
__device__ float g_mskP[NSPLIT * MSK_TOT];   // split-K conv partials (mask logits)
__device__ float g_wt[WT_TOT];               // dcn weights, c-major: [kk][c*64 + o]
__device__ float g_cw[CW_TOT];               // conv weights transposed
__device__ float g_outP5[2 * PCH];
__device__ float g_outP7[4 * PCH];

// ---- f32x2 packed helpers (sm_103a) ----
using u64 = unsigned long long;
__device__ __forceinline__ u64 pack2(float a, float b) {
    u64 r; asm("mov.b64 %0, {%1, %2};" : "=l"(r) : "f"(a), "f"(b)); return r;
}
__device__ __forceinline__ void ffma2(u64& d, u64 a, u64 b) {
    asm("fma.rn.f32x2 %0, %1, %2, %3;" : "=l"(d) : "l"(a), "l"(b), "l"(d));
}
__device__ __forceinline__ float2 unpack2(u64 v) {
    float x, y; asm("mov.b64 {%0, %1}, %2;" : "=f"(x), "=f"(y) : "l"(v));
    return make_float2(x, y);
}
__device__ __forceinline__ unsigned smem_u32(const void* p) {
    unsigned a;
    asm("{ .reg .u64 t; cvta.to.shared.u64 t, %1; cvt.u32.u64 %0, t; }"
        : "=r"(a) : "l"(p));
    return a;
}
__device__ __forceinline__ void cp_async16(unsigned saddr, const void* gptr) {
    asm volatile("cp.async.cg.shared.global [%0], [%1], 16;"
                 :: "r"(saddr), "l"(gptr));
}
__device__ __forceinline__ void cp_commit() {
    asm volatile("cp.async.commit_group;");
}
__device__ __forceinline__ void cp_wait0() {
    asm volatile("cp.async.wait_group 0;");
}

// ---------------------------------------------------------------------------
// Prep: transpose conv weights + dcn weights
// ---------------------------------------------------------------------------
template<int K, int NG>
__device__ __forceinline__ void cw_fill(
    int j, int base, const float* __restrict__ wo, const float* __restrict__ wm)
{
    constexpr int KK = K * K;
    const int lc  = j & 15;
    const int tap = (j >> 4) % KK;
    const int t   = (j >> 4) / KK;
    const int grp = t % NG;
    const int ci  = t / NG;
    const int co  = grp * 16 + lc;
    float v = 0.f;
    if (co < 2 * KK)        v = wo[(co * IC + ci) * KK + tap];
    else if (co < 3 * KK)   v = wm[((co - 2 * KK) * IC + ci) * KK + tap];
    g_cw[base + j] = v;
}

__global__ void prep_weights(
    const float* __restrict__ w3o, const float* __restrict__ w3m,
    const float* __restrict__ w5o, const float* __restrict__ w5m,
    const float* __restrict__ w7o, const float* __restrict__ w7m,
    const float* __restrict__ d3,  const float* __restrict__ d5,
    const float* __restrict__ d7)
{
    int i = blockIdx.x * 256 + threadIdx.x;
    if (i < CW_TOT) {
        if (i < CW_B5)       cw_fill<3, 2>(i,          CW_B3, w3o, w3m);
        else if (i < CW_B7)  cw_fill<5, 5>(i - CW_B5,  CW_B5, w5o, w5m);
        else                 cw_fill<7,10>(i - CW_B7,  CW_B7, w7o, w7m);
    } else {
        int i2 = i - CW_TOT;
        if (i2 < WT_TOT) {
            if (i2 < WT_B5) {
                int kk = i2 >> 12, r = i2 & 4095, c = r >> 6, o = r & 63;
                g_wt[i2] = d3[(o * 64 + c) * 9 + kk];
            } else if (i2 < WT_B7) {
                int j = i2 - WT_B5;
                int kk = j >> 12, r = j & 4095, c = r >> 6, o = r & 63;
                g_wt[i2] = d5[(o * 64 + c) * 25 + kk];
            } else {
                int j = i2 - WT_B7;
                int kk = j >> 12, r = j & 4095, c = r >> 6, o = r & 63;
                g_wt[i2] = d7[(o * 64 + c) * 49 + kk];
            }
        }
    }
}

// ---------------------------------------------------------------------------
// Conv body: 16x16 spatial tile, 128 threads, 2 px x 16 co, split-K over ci.
// Double-buffered smem, register prefetch, 1 sync per ci.
// ---------------------------------------------------------------------------
template<int K, int NG>
__device__ __forceinline__ void conv_body(
    int lb, const float* __restrict__ x, int cwbase,
    int offbase, int mskbase, float* sx2, float* sw2)
{
    constexpr int KK  = K * K;
    constexpr int PAD = K / 2;
    constexpr int TS  = 16 + K - 1;
    constexpr int P   = TS | 1;
    constexpr int WN  = KK * 16;
    constexpr int WLOAD = (WN + 127) / 128;
    constexpr int TN  = TS * TS;
    constexpr int TLOAD = (TN + 127) / 128;
    constexpr int SXSZ = TS * P;

    const int s    = lb & 3;
    int r          = lb >> 2;
    const int tile = r % 25;  r /= 25;
    const int grp  = r % NG;
    const int b    = r / NG;

    const int tid = threadIdx.x;
    const int tx  = tid & 15;
    const int ty  = tid >> 4;
    const int bx0 = (tile % 5) * 16;
    const int by0 = (tile / 5) * 16;
    const int co0 = grp * 16;
    const int ci0 = s * CICHUNK;

    u64 acc0[8], acc1[8];
    #pragma unroll
    for (int i = 0; i < 8; i++) { acc0[i] = 0ull; acc1[i] = 0ull; }

    float treg[TLOAD];
    float wreg[WLOAD];

    auto fetch = [&](int ci) {
        const float* xp = x + (b * IC + ci) * IHW;
        #pragma unroll
        for (int j = 0; j < TLOAD; j++) {
            const int idx = tid + j * 128;
            float v = 0.f;
            if (idx < TN) {
                const int ry = idx / TS, rx = idx - ry * TS;
                const int gy = by0 - PAD + ry, gx = bx0 - PAD + rx;
                if (gy >= 0 && gy < IH && gx >= 0 && gx < IW) v = xp[gy * IW + gx];
            }
            treg[j] = v;
        }
        const float* wp = g_cw + cwbase + (size_t)(ci * NG + grp) * WN;
        #pragma unroll
        for (int j = 0; j < WLOAD; j++) {
            const int idx = tid + j * 128;
            wreg[j] = (idx < WN) ? wp[idx] : 0.f;
        }
    };
    auto stage = [&](int buf) {
        float* sx = sx2 + buf * SXSZ;
        #pragma unroll
        for (int j = 0; j < TLOAD; j++) {
            const int idx = tid + j * 128;
            if (idx < TN) {
                const int ry = idx / TS, rx = idx - ry * TS;
                sx[ry * P + rx] = treg[j];
            }
        }
        float* sw = sw2 + buf * WN;
        #pragma unroll
        for (int j = 0; j < WLOAD; j++) {
            const int idx = tid + j * 128;
            if (idx < WN) sw[idx] = wreg[j];
        }
    };

    fetch(ci0);
    stage(0);
    __syncthreads();

    for (int ss = 0; ss < CICHUNK; ss++) {
        if (ss + 1 < CICHUNK) fetch(ci0 + ss + 1);

        const float* sx = sx2 + (ss & 1) * SXSZ;
        const float* sw = sw2 + (ss & 1) * WN;
        #pragma unroll
        for (int tap = 0; tap < KK; tap++) {
            const int dy = tap / K, dx = tap - dy * K;
            const float xv0 = sx[(ty + dy) * P + tx + dx];
            const float xv1 = sx[(ty + 8 + dy) * P + tx + dx];
            const u64 xp0 = pack2(xv0, xv0);
            const u64 xp1 = pack2(xv1, xv1);
            const u64* w2 = reinterpret_cast<const u64*>(&sw[tap * 16]);
            #pragma unroll
            for (int i = 0; i < 8; i++) {
                u64 w = w2[i];
                ffma2(acc0[i], xp0, w);
                ffma2(acc1[i], xp1, w);
            }
        }

        if (ss + 1 < CICHUNK) stage((ss + 1) & 1);
        __syncthreads();
    }

    float* op = g_offP + (size_t)s * OFF_TOT + offbase;
    float* mp = g_mskP + (size_t)s * MSK_TOT + mskbase;
    const int oy = by0 + ty, ox = bx0 + tx;
    const int idx0 = oy * IW + ox;
    const int idx1 = (oy + 8) * IW + ox;
    #pragma unroll
    for (int i = 0; i < 8; i++) {
        float2 v0 = unpack2(acc0[i]);
        float2 v1 = unpack2(acc1[i]);
        #pragma unroll
        for (int h = 0; h < 2; h++) {
            const int co = co0 + 2 * i + h;
            const float a0 = h ? v0.y : v0.x;
            const float a1 = h ? v1.y : v1.x;
            if (co < 2 * KK) {
                op[(b * 2 * KK + co) * IHW + idx0] = a0;
                op[(b * 2 * KK + co) * IHW + idx1] = a1;
            } else if (co < 3 * KK) {
                const int cm = co - 2 * KK;
                mp[(b * KK + cm) * IHW + idx0] = a0;
                mp[(b * KK + cm) * IHW + idx1] = a1;
            }
        }
    }
}

// Merged conv, branch-interleaved: groups of 17 blocks = 2 k3 + 5 k5 + 10 k7.
__global__ void __launch_bounds__(128) conv_all(const float* __restrict__ x)
{
    __shared__ __align__(16) float sx2[2 * 22 * 23];
    __shared__ __align__(16) float sw2[2 * 49 * 16];

    const int g = blockIdx.x / 17;
    const int u = blockIdx.x % 17;

    if (u < 2)
        conv_body<3, 2>(g * 2 + u,        x, CW_B3, OFF_B3, MSK_B3, sx2, sw2);
    else if (u < 7)
        conv_body<5, 5>(g * 5 + (u - 2),  x, CW_B5, OFF_B5, MSK_B5, sx2, sw2);
    else
        conv_body<7,10>(g * 10 + (u - 7), x, CW_B7, OFF_B7, MSK_B7, sx2, sw2);
}

// ---------------------------------------------------------------------------
// Sample body: 128 pixels/block, 256 threads, taps [kk0,kk1).
// Split-K conv partials are summed INLINE (+bias, sigmoid) — no reduce pass.
// Gather: thread = 1 pixel x 32 channels (NCHW scalar loads, pixel-coalesced).
// Matvec: thread = 4 o x 8 px, f32x2 over pixel pairs.
// Weights loaded via cp.async global->smem (no register staging).
// ---------------------------------------------------------------------------
template<int K>
__device__ __forceinline__ void sample_body(
    int tile, const float* __restrict__ x, float* __restrict__ outp,
    int CS, int kk0, int kk1,
    int offbase, int mskbase, int wtbase,
    const float* __restrict__ b_off, const float* __restrict__ b_msk,
    float* s_w, float* s_samp)
{
    constexpr int KK  = K * K;
    constexpr int PAD = K / 2;
    constexpr int SP  = 128;

    const float* offp = g_offP + offbase;
    const float* mskp = g_mskP + mskbase;
    const float* wtp  = g_wt  + wtbase;

    const int tid  = threadIdx.x;
    const int pix0 = tile * 128;
    const int b    = pix0 / IHW;
    const int rem0 = pix0 - b * IHW;

    const int o0 = tid & 15;
    const int pb = (tid >> 4) * 8;
    const int sp = tid & 127;
    const int sc = tid >> 7;

    const int rem = rem0 + sp;
    const int ph  = rem / IW;
    const int pw  = rem - ph * IW;

    const unsigned swbase = smem_u32(s_w) + tid * 16;

    u64 acc[4][4];
    #pragma unroll
    for (int q = 0; q < 4; q++)
        #pragma unroll
        for (int j = 0; j < 4; j++) acc[q][j] = 0ull;

    for (int kk = kk0; kk < kk1; kk++) {
        // async weight slice load: 256 threads x 4 x 16B = 16KB
        {
            const float* wsrc = wtp + kk * 4096 + tid * 4;
            #pragma unroll
            for (int j = 0; j < 4; j++)
                cp_async16(swbase + j * 4096, wsrc + j * 1024);
            cp_commit();
        }

        // inline split-K reduce of offsets/mask (+bias, sigmoid), then gather
        {
            const int oidx = (b * 2 * KK + 2 * kk) * IHW + rem;
            const int midx = (b * KK + kk) * IHW + rem;
            const float oy = offp[oidx] + offp[OFF_TOT + oidx]
                           + offp[2 * (size_t)OFF_TOT + oidx]
                           + offp[3 * (size_t)OFF_TOT + oidx] + b_off[2 * kk];
            const float ox = offp[oidx + IHW] + offp[OFF_TOT + oidx + IHW]
                           + offp[2 * (size_t)OFF_TOT + oidx + IHW]
                           + offp[3 * (size_t)OFF_TOT + oidx + IHW] + b_off[2 * kk + 1];
            const float ml = mskp[midx] + mskp[MSK_TOT + midx]
                           + mskp[2 * (size_t)MSK_TOT + midx]
                           + mskp[3 * (size_t)MSK_TOT + midx] + b_msk[kk];
            const float m  = 1.f / (1.f + expf(-ml));

            const float py = (float)(ph - PAD + kk / K) + oy;
            const float px = (float)(pw - PAD + kk % K) + ox;
            const float y0f = floorf(py), x0f = floorf(px);
            const int   y0  = (int)y0f,   x0  = (int)x0f;
            const float wy1 = py - y0f, wx1 = px - x0f;
            const float wy0 = 1.f - wy1, wx0 = 1.f - wx1;
            const bool vy0 = (y0 >= 0) && (y0 < IH);
            const bool vy1 = (y0 + 1 >= 0) && (y0 + 1 < IH);
            const bool vx0 = (x0 >= 0) && (x0 < IW);
            const bool vx1 = (x0 + 1 >= 0) && (x0 + 1 < IW);
            const int y0c = min(max(y0, 0), IH - 1);
            const int y1c = min(max(y0 + 1, 0), IH - 1);
            const int x0c = min(max(x0, 0), IW - 1);
            const int x1c = min(max(x0 + 1, 0), IW - 1);
            const float w00 = wy0 * wx0 * ((vy0 && vx0) ? 1.f : 0.f) * m;
            const float w01 = wy0 * wx1 * ((vy0 && vx1) ? 1.f : 0.f) * m;
            const float w10 = wy1 * wx0 * ((vy1 && vx0) ? 1.f : 0.f) * m;
            const float w11 = wy1 * wx1 * ((vy1 && vx1) ? 1.f : 0.f) * m;
            const int i00 = y0c * IW + x0c, i01 = y0c * IW + x1c;
            const int i10 = y1c * IW + x0c, i11 = y1c * IW + x1c;
            const float* base = x + (b * IC + sc * 32) * IHW;
            #pragma unroll 8
            for (int j = 0; j < 32; j++) {
                const float* xp = base + j * IHW;
                float v = w00 * xp[i00] + w01 * xp[i01]
                        + w10 * xp[i10] + w11 * xp[i11];
                s_samp[(sc * 32 + j) * SP + sp] = v;
            }
        }

        cp_wait0();
        __syncthreads();

        #pragma unroll 8
        for (int c = 0; c < 64; c++) {
            const float* wrow = &s_w[c * 64];
            const float4 sA = *(const float4*)&s_samp[c * SP + pb];
            const float4 sB = *(const float4*)&s_samp[c * SP + pb + 4];
            const u64 s0 = pack2(sA.x, sA.y);
            const u64 s1 = pack2(sA.z, sA.w);
            const u64 s2 = pack2(sB.x, sB.y);
            const u64 s3 = pack2(sB.z, sB.w);
            #pragma unroll
            for (int q = 0; q < 4; q++) {
                const float wv = wrow[o0 + 16 * q];
                const u64 wp = pack2(wv, wv);
                ffma2(acc[q][0], wp, s0);
                ffma2(acc[q][1], wp, s1);
                ffma2(acc[q][2], wp, s2);
                ffma2(acc[q][3], wp, s3);
            }
        }
        __syncthreads();
    }

    #pragma unroll
    for (int q = 0; q < 4; q++) {
        const int oo = o0 + q * 16;
        #pragma unroll
        for (int j = 0; j < 4; j++) {
            float2 v = unpack2(acc[q][j]);
            s_samp[oo * SP + pb + 2 * j]     = v.x;
            s_samp[oo * SP + pb + 2 * j + 1] = v.y;
        }
    }
    __syncthreads();
    for (int i = tid; i < 8192; i += 256) {
        const int oo = i >> 7, p = i & 127;
        outp[(b * CS + oo) * IHW + rem0 + p] = s_samp[oo * SP + p];
    }
}

// Balanced sampler: 700 blocks = 100 tiles x 7 tap-chunk units, interleaved.
extern __shared__ float smem_dyn[];
__global__ void __launch_bounds__(256, 2) sample_all(
    const float* __restrict__ x, float* __restrict__ out,
    const float* __restrict__ b3o, const float* __restrict__ b3m,
    const float* __restrict__ b5o, const float* __restrict__ b5m,
    const float* __restrict__ b7o, const float* __restrict__ b7m)
{
    float* s_w    = smem_dyn;           // 4096 floats
    float* s_samp = smem_dyn + 4096;    // 8192 floats

    const int unit = blockIdx.x % 7;
    const int tile = blockIdx.x / 7;

    if (unit == 0) {
        sample_body<3>(tile, x, out, 192, 0, 9,
                       OFF_B3, MSK_B3, WT_B3, b3o, b3m, s_w, s_samp);
    } else if (unit <= 2) {
        const int c = unit - 1;
        const int k0 = c * 13, k1 = (c == 1) ? 25 : 13;
        sample_body<5>(tile, x, g_outP5 + (size_t)c * PCH, 64, k0, k1,
                       OFF_B5, MSK_B5, WT_B5, b5o, b5m, s_w, s_samp);
    } else {
        const int c = unit - 3;
        const int k0 = c * 13, k1 = (c == 3) ? 49 : (c + 1) * 13;
        sample_body<7>(tile, x, g_outP7 + (size_t)c * PCH, 64, k0, k1,
                       OFF_B7, MSK_B7, WT_B7, b7o, b7m, s_w, s_samp);
    }
}

// Fold k5/k7 partials into out channels [64,192)
__global__ void reduce_out(float* __restrict__ out)
{
    int i = blockIdx.x * 256 + threadIdx.x;
    if (i < PCH) {
        const int b     = i / (64 * IHW);
        const int local = i - b * 64 * IHW;
        out[(b * 192 + 64) * IHW + local]  = g_outP5[i] + g_outP5[PCH + i];
        out[(b * 192 + 128) * IHW + local] = g_outP7[i] + g_outP7[PCH + i]
                                           + g_outP7[2 * (size_t)PCH + i]
                                           + g_outP7[3 * (size_t)PCH + i];
    }
}

// ---------------------------------------------------------------------------
extern "C" void kernel_launch(void* const* d_in, const int* in_sizes, int n_in,
                              void* d_out, int out_size)
{
    const float* x = (const float*)d_in[0];
    float* out = (float*)d_out;

    prep_weights<<<(CW_TOT + WT_TOT + 255) / 256, 256>>>(
        (const float*)d_in[1],  (const float*)d_in[3],
        (const float*)d_in[6],  (const float*)d_in[8],
        (const float*)d_in[11], (const float*)d_in[13],
        (const float*)d_in[5],  (const float*)d_in[10], (const float*)d_in[15]);

    conv_all<<<3400, 128>>>(x);

    sample_all<<<700, 256, 48 * 1024>>>(x, out,
        (const float*)d_in[2],  (const float*)d_in[4],
        (const float*)d_in[7],  (const float*)d_in[9],
        (const float*)d_in[12], (const float*)d_in[14]);

    reduce_out<<<(PCH + 255) / 256, 256>>>(out);
}